// round 1
// baseline (speedup 1.0000x reference)
#include <cuda_runtime.h>
#include <cuda_bf16.h>
#include <cstddef>

// Problem constants
#define S   2048
#define H   2048
#define NH  16
#define D   128          // head dim
#define D2  256          // 2*D (q/k packed mu|sigma)

// ---------------- scratch (static device globals; no allocations) ------------
__device__ float g_Q[(size_t)S * (2 * H)];       // [S, 4096]  X @ Wq^T
__device__ float g_K[(size_t)S * (2 * H)];       // [S, 4096]  X @ Wk^T
__device__ float g_V[(size_t)S * H];             // [S, 2048]  X @ Wv^T
__device__ float g_QW[(size_t)NH * S * D];       // [h, s, d] rope'd q_w
__device__ float g_KW[(size_t)NH * S * D];       // [h, s, d] rope'd k_w
__device__ float g_AK[(size_t)NH * S];           // -0.5*(k_sq + logdet_k)
__device__ float g_SC[(size_t)NH * S * S];       // scores / probs (268 MB)
__device__ float g_AO[(size_t)S * H];            // attn output [s, h*128+d]

// ---------------- generic SGEMM: C = A * op(B) (+ bias[n]) -------------------
// TN (TRANSB=true):  C[m,n] = sum_k A[m*lda+k] * B[n*ldb+k]   (torch Linear)
// NN (TRANSB=false): C[m,n] = sum_k A[m*lda+k] * B[k*ldb+n]
// Batched over blockIdx.z with element strides sA/sB/sC/sBias.
// Requires M%128==0, N%128==0, K%8==0, 16B-aligned rows (all true here).
#define BM 128
#define BN 128
#define BK 8

template <bool TRANSB, bool BIAS>
__global__ void __launch_bounds__(256)
sgemm_kernel(int M, int N, int K,
             const float* __restrict__ A, int lda, size_t sA,
             const float* __restrict__ B, int ldb, size_t sB,
             float* __restrict__ C, int ldc, size_t sC,
             const float* __restrict__ bias, size_t sBias)
{
    const int z = blockIdx.z;
    A += (size_t)z * sA;
    B += (size_t)z * sB;
    C += (size_t)z * sC;
    if (BIAS) bias += (size_t)z * sBias;

    const int m0 = blockIdx.y * BM;
    const int n0 = blockIdx.x * BN;

    __shared__ float As[BK][BM];
    __shared__ float Bs[BK][BN];

    const int t  = threadIdx.x;          // 0..255
    const int tx = t & 15;               // col group
    const int ty = t >> 4;               // row group

    float acc[8][8];
#pragma unroll
    for (int i = 0; i < 8; i++)
#pragma unroll
        for (int j = 0; j < 8; j++) acc[i][j] = 0.f;

    // A-load indices (also used for TN B-load)
    const int am = t >> 1;               // 0..127
    const int ak = (t & 1) * 4;          // 0 or 4
    // NN B-load indices
    const int bk = t >> 5;               // 0..7
    const int bn = (t & 31) * 4;         // 0..124

    const int nk = K / BK;
    for (int kt = 0; kt < nk; kt++) {
        const int k0 = kt * BK;

        // --- load A tile (row-major, k contiguous) ---
        {
            const float4 v = *(const float4*)(A + (size_t)(m0 + am) * lda + k0 + ak);
            As[ak + 0][am] = v.x;
            As[ak + 1][am] = v.y;
            As[ak + 2][am] = v.z;
            As[ak + 3][am] = v.w;
        }
        // --- load B tile ---
        if (TRANSB) {
            const float4 v = *(const float4*)(B + (size_t)(n0 + am) * ldb + k0 + ak);
            Bs[ak + 0][am] = v.x;
            Bs[ak + 1][am] = v.y;
            Bs[ak + 2][am] = v.z;
            Bs[ak + 3][am] = v.w;
        } else {
            const float4 v = *(const float4*)(B + (size_t)(k0 + bk) * ldb + n0 + bn);
            *(float4*)&Bs[bk][bn] = v;
        }
        __syncthreads();

#pragma unroll
        for (int kk = 0; kk < BK; kk++) {
            float4 a0 = *(const float4*)&As[kk][ty * 8];
            float4 a1 = *(const float4*)&As[kk][ty * 8 + 4];
            float4 b0 = *(const float4*)&Bs[kk][tx * 8];
            float4 b1 = *(const float4*)&Bs[kk][tx * 8 + 4];
            float a[8] = {a0.x, a0.y, a0.z, a0.w, a1.x, a1.y, a1.z, a1.w};
            float b[8] = {b0.x, b0.y, b0.z, b0.w, b1.x, b1.y, b1.z, b1.w};
#pragma unroll
            for (int i = 0; i < 8; i++)
#pragma unroll
                for (int j = 0; j < 8; j++) acc[i][j] += a[i] * b[j];
        }
        __syncthreads();
    }

    const int row0 = m0 + ty * 8;
    const int col0 = n0 + tx * 8;
    float bj[8];
    if (BIAS) {
#pragma unroll
        for (int j = 0; j < 8; j++) bj[j] = bias[col0 + j];
    }
#pragma unroll
    for (int i = 0; i < 8; i++) {
        float4 o0, o1;
        if (BIAS) {
            o0 = make_float4(acc[i][0] + bj[0], acc[i][1] + bj[1],
                             acc[i][2] + bj[2], acc[i][3] + bj[3]);
            o1 = make_float4(acc[i][4] + bj[4], acc[i][5] + bj[5],
                             acc[i][6] + bj[6], acc[i][7] + bj[7]);
        } else {
            o0 = make_float4(acc[i][0], acc[i][1], acc[i][2], acc[i][3]);
            o1 = make_float4(acc[i][4], acc[i][5], acc[i][6], acc[i][7]);
        }
        float* cp = C + (size_t)(row0 + i) * ldc + col0;
        *(float4*)cp       = o0;
        *(float4*)(cp + 4) = o1;
    }
}

// ---------------- softplus + variance weighting + RoPE -----------------------
// One block of 128 threads per (s, h). raw is [S, 4096]: cols h*256 + (mu:0..127 | sigma:128..255)
__global__ void __launch_bounds__(128)
transform_kernel(const float* __restrict__ raw,
                 const float* __restrict__ cosT,
                 const float* __restrict__ sinT,
                 float* __restrict__ W,          // [NH, S, D]
                 float* __restrict__ AK,         // [NH, S] or null
                 int writeAK)
{
    const int s = blockIdx.x;
    const int h = blockIdx.y;
    const int d = threadIdx.x;

    const float* base = raw + (size_t)s * (2 * H) + h * D2;
    float mu = base[d];
    float sr = base[D + d];
    // stable softplus
    float sp = (sr > 20.f) ? sr : log1pf(expf(sr));
    float sigma = sp + 1e-4f;
    float w = mu * rsqrtf(sigma);

    __shared__ float sw[D];
    sw[d] = w;
    __syncthreads();
    float rh = (d < 64) ? -sw[d + 64] : sw[d - 64];
    float wr = w * cosT[(size_t)s * D + d] + rh * sinT[(size_t)s * D + d];

    W[((size_t)h * S + s) * D + d] = wr;

    if (writeAK) {
        __shared__ float red[D];
        red[d] = wr * wr + logf(sigma);
        __syncthreads();
#pragma unroll
        for (int o = 64; o > 0; o >>= 1) {
            if (d < o) red[d] += red[d + o];
            __syncthreads();
        }
        if (d == 0) AK[(size_t)h * S + s] = -0.5f * red[0];
    }
}

// ---------------- row softmax over the key dimension --------------------------
__global__ void __launch_bounds__(256)
softmax_kernel(float* __restrict__ SC)
{
    const int q = blockIdx.x;
    const int h = blockIdx.y;
    float* row = SC + ((size_t)h * S + q) * S;
    const int t = threadIdx.x;

    __shared__ float red[256];

    float m = -1e30f;
    for (int i = t; i < S; i += 256) m = fmaxf(m, row[i]);
    red[t] = m;
    __syncthreads();
#pragma unroll
    for (int o = 128; o > 0; o >>= 1) {
        if (t < o) red[t] = fmaxf(red[t], red[t + o]);
        __syncthreads();
    }
    m = red[0];
    __syncthreads();

    float sum = 0.f;
    for (int i = t; i < S; i += 256) {
        float e = __expf(row[i] - m);
        row[i] = e;
        sum += e;
    }
    red[t] = sum;
    __syncthreads();
#pragma unroll
    for (int o = 128; o > 0; o >>= 1) {
        if (t < o) red[t] += red[t + o];
        __syncthreads();
    }
    const float inv = 1.f / red[0];
    for (int i = t; i < S; i += 256) row[i] *= inv;
}

// ---------------- launch ------------------------------------------------------
extern "C" void kernel_launch(void* const* d_in, const int* in_sizes, int n_in,
                              void* d_out, int out_size)
{
    const float* X    = (const float*)d_in[0];  // [1, 2048, 2048]
    const float* cosT = (const float*)d_in[1];  // [2048, 128]
    const float* sinT = (const float*)d_in[2];  // [2048, 128]
    const float* w_q  = (const float*)d_in[3];  // [4096, 2048]
    const float* w_k  = (const float*)d_in[4];  // [4096, 2048]
    const float* w_v  = (const float*)d_in[5];  // [2048, 2048]
    const float* w_o  = (const float*)d_in[6];  // [2048, 2048]
    float* out = (float*)d_out;                 // [1, 2048, 2048]

    float *Q, *K, *V, *QW, *KW, *AK, *SC, *AO;
    cudaGetSymbolAddress((void**)&Q,  g_Q);
    cudaGetSymbolAddress((void**)&K,  g_K);
    cudaGetSymbolAddress((void**)&V,  g_V);
    cudaGetSymbolAddress((void**)&QW, g_QW);
    cudaGetSymbolAddress((void**)&KW, g_KW);
    cudaGetSymbolAddress((void**)&AK, g_AK);
    cudaGetSymbolAddress((void**)&SC, g_SC);
    cudaGetSymbolAddress((void**)&AO, g_AO);

    // 1) Q = X @ Wq^T : [2048, 4096]
    sgemm_kernel<true, false><<<dim3(4096 / BN, S / BM, 1), 256>>>(
        S, 4096, H, X, H, 0, w_q, H, 0, Q, 4096, 0, nullptr, 0);
    // 2) K = X @ Wk^T
    sgemm_kernel<true, false><<<dim3(4096 / BN, S / BM, 1), 256>>>(
        S, 4096, H, X, H, 0, w_k, H, 0, K, 4096, 0, nullptr, 0);
    // 3) V = X @ Wv^T : [2048, 2048]
    sgemm_kernel<true, false><<<dim3(H / BN, S / BM, 1), 256>>>(
        S, H, H, X, H, 0, w_v, H, 0, V, H, 0, nullptr, 0);

    // 4) transform Q (no AK), 5) transform K (with AK)
    transform_kernel<<<dim3(S, NH), 128>>>(Q, cosT, sinT, QW, nullptr, 0);
    transform_kernel<<<dim3(S, NH), 128>>>(K, cosT, sinT, KW, AK, 1);

    // 6) scores per head: SC[h] = QW[h] @ KW[h]^T + AK[h][n]
    sgemm_kernel<true, true><<<dim3(S / BN, S / BM, NH), 256>>>(
        S, S, D,
        QW, D, (size_t)S * D,
        KW, D, (size_t)S * D,
        SC, S, (size_t)S * S,
        AK, (size_t)S);

    // 7) softmax over keys
    softmax_kernel<<<dim3(S, NH), 256>>>(SC);

    // 8) AO[:, h*128:...] = P[h] @ V[:, h*128:...]   (NN form)
    sgemm_kernel<false, false><<<dim3(D / BN, S / BM, NH), 256>>>(
        S, D, S,
        SC, S, (size_t)S * S,
        V,  H, (size_t)D,
        AO, H, (size_t)D,
        nullptr, 0);

    // 9) out = AO @ Wo^T
    sgemm_kernel<true, false><<<dim3(H / BN, S / BM, 1), 256>>>(
        S, H, H, AO, H, 0, w_o, H, 0, out, H, 0, nullptr, 0);
}

// round 3
// speedup vs baseline: 2.0248x; 2.0248x over previous
#include <cuda_runtime.h>
#include <cuda_bf16.h>
#include <cstdint>
#include <cstddef>

#define S   2048
#define H   2048
#define NH  16
#define D   128
typedef __nv_bfloat16 bf16;

// ---------------- scratch ----------------------------------------------------
__device__ bf16  g_Xhi[(size_t)S * H],  g_Xlo[(size_t)S * H];
__device__ bf16  g_wqhi[(size_t)2 * H * H], g_wqlo[(size_t)2 * H * H];
__device__ bf16  g_wkhi[(size_t)2 * H * H], g_wklo[(size_t)2 * H * H];
__device__ bf16  g_wvhi[(size_t)H * H], g_wvlo[(size_t)H * H];
__device__ bf16  g_wohi[(size_t)H * H], g_wolo[(size_t)H * H];
__device__ float g_Qraw[(size_t)S * 2 * H];
__device__ float g_Kraw[(size_t)S * 2 * H];
__device__ float g_Vf[(size_t)S * H];
__device__ bf16  g_QWhi[(size_t)NH * S * D], g_QWlo[(size_t)NH * S * D];
__device__ bf16  g_KWhi[(size_t)NH * S * D], g_KWlo[(size_t)NH * S * D];
__device__ float g_AK[(size_t)NH * S];
__device__ float g_SC[(size_t)NH * S * S];
__device__ bf16  g_Phi[(size_t)NH * S * S], g_Plo[(size_t)NH * S * S];
__device__ bf16  g_VThi[(size_t)NH * D * S], g_VTlo[(size_t)NH * D * S];
__device__ bf16  g_AOhi[(size_t)S * H], g_AOlo[(size_t)S * H];

// ---------------- helpers -----------------------------------------------------
__device__ __forceinline__ uint32_t smem_u32(const void* p) {
    uint32_t a;
    asm("{ .reg .u64 t; cvta.to.shared.u64 t, %1; cvt.u32.u64 %0, t; }" : "=r"(a) : "l"(p));
    return a;
}
__device__ __forceinline__ void cp16(uint32_t dst, const void* src) {
    asm volatile("cp.async.cg.shared.global [%0], [%1], 16;" :: "r"(dst), "l"(src) : "memory");
}
#define CP_COMMIT() asm volatile("cp.async.commit_group;" ::: "memory")
#define CP_WAIT2()  asm volatile("cp.async.wait_group 2;" ::: "memory")

__device__ __forceinline__ void ldm_x4(uint32_t r[4], uint32_t addr) {
    asm volatile("ldmatrix.sync.aligned.m8n8.x4.shared.b16 {%0,%1,%2,%3}, [%4];"
                 : "=r"(r[0]), "=r"(r[1]), "=r"(r[2]), "=r"(r[3]) : "r"(addr));
}
__device__ __forceinline__ void mma_bf16(float c[4], const uint32_t a[4],
                                         uint32_t b0, uint32_t b1) {
    asm volatile(
        "mma.sync.aligned.m16n8k16.row.col.f32.bf16.bf16.f32 "
        "{%0,%1,%2,%3}, {%4,%5,%6,%7}, {%8,%9}, {%0,%1,%2,%3};"
        : "+f"(c[0]), "+f"(c[1]), "+f"(c[2]), "+f"(c[3])
        : "r"(a[0]), "r"(a[1]), "r"(a[2]), "r"(a[3]), "r"(b0), "r"(b1));
}
__device__ __forceinline__ void split2(float x, bf16& h, bf16& l) {
    h = __float2bfloat16_rn(x);
    l = __float2bfloat16_rn(x - __bfloat162float(h));
}

// ---------------- HMMA GEMM: C = (Ahi+Alo)·(Bhi+Blo)^T (+bias[n]) ------------
// A: [M,K] k-major bf16 hi/lo; B: [N,K] k-major bf16 hi/lo.
// CTA 128x128, BK=32, 8 warps (2m x 4n), each warp 64x32.
// smem per stage: 4 matrices (Ahi,Alo,Bhi,Blo) x [2 k16][128 rows][32B], swizzled.
#define BK 32
#define MAT_B   8192          // 2*128*32
#define STAGE_B (4 * MAT_B)   // 32KB
#define NSTG 3
#define GEMM_SMEM (NSTG * STAGE_B)

// swizzled in-matrix offset for (k16, row, half16B)
__device__ __forceinline__ uint32_t sw_off(int k16, int row, int half) {
    return (uint32_t)(k16 * 4096 + row * 32 + ((half ^ ((row >> 2) & 1)) << 4));
}

template <bool BIAS, bool EPI_BF16>
__global__ void __launch_bounds__(256, 1)
gemm_kernel(int M, int N, int K,
            const bf16* __restrict__ Ahi, const bf16* __restrict__ Alo, int lda, size_t sA,
            const bf16* __restrict__ Bhi, const bf16* __restrict__ Blo, int ldb, size_t sB,
            float* __restrict__ C, int ldc, size_t sC,
            const float* __restrict__ bias, size_t sBias,
            bf16* __restrict__ Chi, bf16* __restrict__ Clo)
{
    extern __shared__ char smem[];
    const uint32_t sbase = smem_u32(smem);
    const int tid  = threadIdx.x;
    const int lane = tid & 31;
    const int wid  = tid >> 5;
    const int wm0  = (wid & 1) * 64;    // warp m offset in tile
    const int wn0  = (wid >> 1) * 32;   // warp n offset in tile

    const int z = blockIdx.z;
    Ahi += (size_t)z * sA;  Alo += (size_t)z * sA;
    Bhi += (size_t)z * sB;  Blo += (size_t)z * sB;
    if (EPI_BF16) { Chi += (size_t)z * sC; Clo += (size_t)z * sC; }
    else          { C   += (size_t)z * sC; }
    if (BIAS) bias += (size_t)z * sBias;

    const int m0 = blockIdx.y * 128;
    const int n0 = blockIdx.x * 128;

    // per-thread load coords (8 x 16B chunks per stage)
    const int lrow  = tid >> 2;          // 0..63 (x2 via +64)
    const int lc    = tid & 3;
    const int lk16  = lc >> 1;
    const int lhalf = lc & 1;

    auto load_stage = [&](int kt, int stg) {
        const int k0 = kt * BK;
        const uint32_t sb = sbase + stg * STAGE_B;
        const int kel = k0 + lk16 * 16 + lhalf * 8;
#pragma unroll
        for (int i = 0; i < 2; i++) {
            const int row = lrow + i * 64;
            const uint32_t so = sw_off(lk16, row, lhalf);
            cp16(sb + so,             Ahi + (size_t)(m0 + row) * lda + kel);
            cp16(sb + MAT_B + so,     Alo + (size_t)(m0 + row) * lda + kel);
            cp16(sb + 2 * MAT_B + so, Bhi + (size_t)(n0 + row) * ldb + kel);
            cp16(sb + 3 * MAT_B + so, Blo + (size_t)(n0 + row) * ldb + kel);
        }
    };

    float acc[4][4][4];
#pragma unroll
    for (int i = 0; i < 4; i++)
#pragma unroll
        for (int j = 0; j < 4; j++)
#pragma unroll
            for (int r = 0; r < 4; r++) acc[i][j][r] = 0.f;

    const int nk = K / BK;
    load_stage(0, 0); CP_COMMIT();
    load_stage(1, 1); CP_COMMIT();

    for (int kt = 0; kt < nk; kt++) {
        if (kt + 2 < nk) load_stage(kt + 2, (kt + 2) % NSTG);
        CP_COMMIT();
        CP_WAIT2();
        __syncthreads();

        const uint32_t sb = sbase + (kt % NSTG) * STAGE_B;
#pragma unroll
        for (int k16 = 0; k16 < 2; k16++) {
            // A fragments (hi/lo), 4 m-tiles of 16
            uint32_t ah[4][4], al[4][4];
#pragma unroll
            for (int mt = 0; mt < 4; mt++) {
                const int row = wm0 + mt * 16 + (lane & 15);
                const uint32_t off = sw_off(k16, row, lane >> 4);
                ldm_x4(ah[mt], sb + off);
                ldm_x4(al[mt], sb + MAT_B + off);
            }
            // B fragments (hi/lo): 2 x (16n x 16k) -> 4 n-tiles of 8
            uint32_t bh[2][4], bl[2][4];
#pragma unroll
            for (int nt16 = 0; nt16 < 2; nt16++) {
                const int row = wn0 + nt16 * 16 + (lane & 15);
                const uint32_t off = sw_off(k16, row, lane >> 4);
                ldm_x4(bh[nt16], sb + 2 * MAT_B + off);
                ldm_x4(bl[nt16], sb + 3 * MAT_B + off);
            }
#pragma unroll
            for (int mt = 0; mt < 4; mt++) {
#pragma unroll
                for (int nt = 0; nt < 4; nt++) {
                    const int g = nt >> 1;          // which 16n group
                    const int p = nt & 1;           // which n8 within group
                    const uint32_t bh0 = bh[g][p],     bh1 = bh[g][p + 2];
                    const uint32_t bl0 = bl[g][p],     bl1 = bl[g][p + 2];
                    mma_bf16(acc[mt][nt], ah[mt], bh0, bh1);
                    mma_bf16(acc[mt][nt], ah[mt], bl0, bl1);
                    mma_bf16(acc[mt][nt], al[mt], bh0, bh1);
                }
            }
        }
        __syncthreads();
    }

    // ---------------- epilogue ----------------
    const int rbase = m0 + wm0 + (lane >> 2);
    const int cbase = n0 + wn0 + (lane & 3) * 2;
#pragma unroll
    for (int mt = 0; mt < 4; mt++) {
#pragma unroll
        for (int nt = 0; nt < 4; nt++) {
            const int row = rbase + mt * 16;
            const int col = cbase + nt * 8;
            float v0 = acc[mt][nt][0], v1 = acc[mt][nt][1];
            float v2 = acc[mt][nt][2], v3 = acc[mt][nt][3];
            if (BIAS) {
                const float b0 = __ldg(bias + col), b1 = __ldg(bias + col + 1);
                v0 += b0; v1 += b1; v2 += b0; v3 += b1;
            }
            if (EPI_BF16) {
                bf16 h0, l0, h1, l1;
                split2(v0, h0, l0); split2(v1, h1, l1);
                __nv_bfloat162 hp; hp.x = h0; hp.y = h1;
                __nv_bfloat162 lp; lp.x = l0; lp.y = l1;
                *reinterpret_cast<__nv_bfloat162*>(Chi + (size_t)row * ldc + col) = hp;
                *reinterpret_cast<__nv_bfloat162*>(Clo + (size_t)row * ldc + col) = lp;
                split2(v2, h0, l0); split2(v3, h1, l1);
                hp.x = h0; hp.y = h1; lp.x = l0; lp.y = l1;
                *reinterpret_cast<__nv_bfloat162*>(Chi + (size_t)(row + 8) * ldc + col) = hp;
                *reinterpret_cast<__nv_bfloat162*>(Clo + (size_t)(row + 8) * ldc + col) = lp;
            } else {
                *reinterpret_cast<float2*>(C + (size_t)row * ldc + col)       = make_float2(v0, v1);
                *reinterpret_cast<float2*>(C + (size_t)(row + 8) * ldc + col) = make_float2(v2, v3);
            }
        }
    }
}

// ---------------- fp32 -> bf16 hi/lo split -----------------------------------
__global__ void split_kernel(const float* __restrict__ x, bf16* __restrict__ hi,
                             bf16* __restrict__ lo, int n4)
{
    int i = blockIdx.x * blockDim.x + threadIdx.x;
    if (i >= n4) return;
    float4 v = reinterpret_cast<const float4*>(x)[i];
    bf16 h[4], l[4];
    split2(v.x, h[0], l[0]); split2(v.y, h[1], l[1]);
    split2(v.z, h[2], l[2]); split2(v.w, h[3], l[3]);
    __nv_bfloat162 hp0; hp0.x = h[0]; hp0.y = h[1];
    __nv_bfloat162 hp1; hp1.x = h[2]; hp1.y = h[3];
    __nv_bfloat162 lp0; lp0.x = l[0]; lp0.y = l[1];
    __nv_bfloat162 lp1; lp1.x = l[2]; lp1.y = l[3];
    reinterpret_cast<__nv_bfloat162*>(hi)[i * 2]     = hp0;
    reinterpret_cast<__nv_bfloat162*>(hi)[i * 2 + 1] = hp1;
    reinterpret_cast<__nv_bfloat162*>(lo)[i * 2]     = lp0;
    reinterpret_cast<__nv_bfloat162*>(lo)[i * 2 + 1] = lp1;
}

// ---------------- softplus + variance weighting + RoPE -----------------------
__global__ void __launch_bounds__(128)
transform_kernel(const float* __restrict__ raw,
                 const float* __restrict__ cosT, const float* __restrict__ sinT,
                 bf16* __restrict__ Whi, bf16* __restrict__ Wlo,
                 float* __restrict__ AK, int writeAK)
{
    const int s = blockIdx.x, h = blockIdx.y, d = threadIdx.x;
    const float* base = raw + (size_t)s * (2 * H) + h * (2 * D);
    float mu = base[d];
    float sr = base[D + d];
    float sp = (sr > 20.f) ? sr : log1pf(expf(sr));
    float sigma = sp + 1e-4f;
    float w = mu * rsqrtf(sigma);

    __shared__ float sw[D];
    sw[d] = w;
    __syncthreads();
    float rh = (d < 64) ? -sw[d + 64] : sw[d - 64];
    float wr = w * cosT[(size_t)s * D + d] + rh * sinT[(size_t)s * D + d];

    bf16 hh, ll;
    split2(wr, hh, ll);
    const size_t o = ((size_t)h * S + s) * D + d;
    Whi[o] = hh;  Wlo[o] = ll;

    if (writeAK) {
        __shared__ float red[D];
        red[d] = wr * wr + logf(sigma);
        __syncthreads();
#pragma unroll
        for (int o2 = 64; o2 > 0; o2 >>= 1) {
            if (d < o2) red[d] += red[d + o2];
            __syncthreads();
        }
        if (d == 0) AK[(size_t)h * S + s] = -0.5f * red[0];
    }
}

// ---------------- V transpose + split ----------------------------------------
__global__ void vtrans_kernel(const float* __restrict__ V,
                              bf16* __restrict__ VThi, bf16* __restrict__ VTlo)
{
    __shared__ float tile[32][33];
    const int s0 = blockIdx.x * 32, d0 = blockIdx.y * 32, h = blockIdx.z;
    const int tx = threadIdx.x, ty = threadIdx.y;
#pragma unroll
    for (int j = 0; j < 4; j++) {
        int r = ty + j * 8;
        tile[r][tx] = V[(size_t)(s0 + r) * H + h * D + d0 + tx];
    }
    __syncthreads();
#pragma unroll
    for (int j = 0; j < 4; j++) {
        int dr = ty + j * 8;
        float v = tile[tx][dr];
        bf16 hh, ll;
        split2(v, hh, ll);
        size_t o = ((size_t)h * D + d0 + dr) * S + s0 + tx;
        VThi[o] = hh;  VTlo[o] = ll;
    }
}

// ---------------- register-resident softmax -> bf16 hi/lo probs --------------
__global__ void __launch_bounds__(256)
softmax_kernel(const float* __restrict__ SC, bf16* __restrict__ Phi, bf16* __restrict__ Plo)
{
    const int q = blockIdx.x, h = blockIdx.y, t = threadIdx.x;
    const size_t base = ((size_t)h * S + q) * S;
    const float* row = SC + base;

    float v[8];
    float4 a = *reinterpret_cast<const float4*>(row + t * 8);
    float4 b = *reinterpret_cast<const float4*>(row + t * 8 + 4);
    v[0] = a.x; v[1] = a.y; v[2] = a.z; v[3] = a.w;
    v[4] = b.x; v[5] = b.y; v[6] = b.z; v[7] = b.w;

    __shared__ float red[256];
    float m = v[0];
#pragma unroll
    for (int i = 1; i < 8; i++) m = fmaxf(m, v[i]);
    red[t] = m;
    __syncthreads();
#pragma unroll
    for (int o = 128; o > 0; o >>= 1) {
        if (t < o) red[t] = fmaxf(red[t], red[t + o]);
        __syncthreads();
    }
    m = red[0];
    __syncthreads();

    float sum = 0.f;
#pragma unroll
    for (int i = 0; i < 8; i++) { v[i] = __expf(v[i] - m); sum += v[i]; }
    red[t] = sum;
    __syncthreads();
#pragma unroll
    for (int o = 128; o > 0; o >>= 1) {
        if (t < o) red[t] += red[t + o];
        __syncthreads();
    }
    const float inv = 1.f / red[0];

#pragma unroll
    for (int j = 0; j < 4; j++) {
        float p0 = v[2 * j] * inv, p1 = v[2 * j + 1] * inv;
        bf16 h0, l0, h1, l1;
        split2(p0, h0, l0); split2(p1, h1, l1);
        __nv_bfloat162 hp; hp.x = h0; hp.y = h1;
        __nv_bfloat162 lp; lp.x = l0; lp.y = l1;
        *reinterpret_cast<__nv_bfloat162*>(Phi + base + t * 8 + 2 * j) = hp;
        *reinterpret_cast<__nv_bfloat162*>(Plo + base + t * 8 + 2 * j) = lp;
    }
}

// ---------------- launch ------------------------------------------------------
extern "C" void kernel_launch(void* const* d_in, const int* in_sizes, int n_in,
                              void* d_out, int out_size)
{
    const float* X    = (const float*)d_in[0];
    const float* cosT = (const float*)d_in[1];
    const float* sinT = (const float*)d_in[2];
    const float* w_q  = (const float*)d_in[3];
    const float* w_k  = (const float*)d_in[4];
    const float* w_v  = (const float*)d_in[5];
    const float* w_o  = (const float*)d_in[6];
    float* out = (float*)d_out;

    bf16 *Xhi, *Xlo, *wqhi, *wqlo, *wkhi, *wklo, *wvhi, *wvlo, *wohi, *wolo;
    float *Qraw, *Kraw, *Vf, *AK, *SC;
    bf16 *QWhi, *QWlo, *KWhi, *KWlo, *Phi, *Plo, *VThi, *VTlo, *AOhi, *AOlo;
    cudaGetSymbolAddress((void**)&Xhi, g_Xhi);   cudaGetSymbolAddress((void**)&Xlo, g_Xlo);
    cudaGetSymbolAddress((void**)&wqhi, g_wqhi); cudaGetSymbolAddress((void**)&wqlo, g_wqlo);
    cudaGetSymbolAddress((void**)&wkhi, g_wkhi); cudaGetSymbolAddress((void**)&wklo, g_wklo);
    cudaGetSymbolAddress((void**)&wvhi, g_wvhi); cudaGetSymbolAddress((void**)&wvlo, g_wvlo);
    cudaGetSymbolAddress((void**)&wohi, g_wohi); cudaGetSymbolAddress((void**)&wolo, g_wolo);
    cudaGetSymbolAddress((void**)&Qraw, g_Qraw); cudaGetSymbolAddress((void**)&Kraw, g_Kraw);
    cudaGetSymbolAddress((void**)&Vf, g_Vf);
    cudaGetSymbolAddress((void**)&QWhi, g_QWhi); cudaGetSymbolAddress((void**)&QWlo, g_QWlo);
    cudaGetSymbolAddress((void**)&KWhi, g_KWhi); cudaGetSymbolAddress((void**)&KWlo, g_KWlo);
    cudaGetSymbolAddress((void**)&AK, g_AK);     cudaGetSymbolAddress((void**)&SC, g_SC);
    cudaGetSymbolAddress((void**)&Phi, g_Phi);   cudaGetSymbolAddress((void**)&Plo, g_Plo);
    cudaGetSymbolAddress((void**)&VThi, g_VThi); cudaGetSymbolAddress((void**)&VTlo, g_VTlo);
    cudaGetSymbolAddress((void**)&AOhi, g_AOhi); cudaGetSymbolAddress((void**)&AOlo, g_AOlo);

    cudaFuncSetAttribute(gemm_kernel<false, false>,
                         cudaFuncAttributeMaxDynamicSharedMemorySize, GEMM_SMEM);
    cudaFuncSetAttribute(gemm_kernel<true, false>,
                         cudaFuncAttributeMaxDynamicSharedMemorySize, GEMM_SMEM);
    cudaFuncSetAttribute(gemm_kernel<false, true>,
                         cudaFuncAttributeMaxDynamicSharedMemorySize, GEMM_SMEM);

    // 0) pre-split inputs & weights
    auto launch_split = [](const float* x, bf16* hi, bf16* lo, size_t n) {
        int n4 = (int)(n / 4);
        split_kernel<<<(n4 + 255) / 256, 256>>>(x, hi, lo, n4);
    };
    launch_split(X,   Xhi,  Xlo,  (size_t)S * H);
    launch_split(w_q, wqhi, wqlo, (size_t)2 * H * H);
    launch_split(w_k, wkhi, wklo, (size_t)2 * H * H);
    launch_split(w_v, wvhi, wvlo, (size_t)H * H);
    launch_split(w_o, wohi, wolo, (size_t)H * H);

    // 1-3) projections
    gemm_kernel<false, false><<<dim3(4096 / 128, S / 128, 1), 256, GEMM_SMEM>>>(
        S, 4096, H, Xhi, Xlo, H, 0, wqhi, wqlo, H, 0,
        Qraw, 4096, 0, nullptr, 0, nullptr, nullptr);
    gemm_kernel<false, false><<<dim3(4096 / 128, S / 128, 1), 256, GEMM_SMEM>>>(
        S, 4096, H, Xhi, Xlo, H, 0, wkhi, wklo, H, 0,
        Kraw, 4096, 0, nullptr, 0, nullptr, nullptr);
    gemm_kernel<false, false><<<dim3(H / 128, S / 128, 1), 256, GEMM_SMEM>>>(
        S, H, H, Xhi, Xlo, H, 0, wvhi, wvlo, H, 0,
        Vf, H, 0, nullptr, 0, nullptr, nullptr);

    // 4-5) transform
    transform_kernel<<<dim3(S, NH), 128>>>(Qraw, cosT, sinT, QWhi, QWlo, nullptr, 0);
    transform_kernel<<<dim3(S, NH), 128>>>(Kraw, cosT, sinT, KWhi, KWlo, AK, 1);

    // 6) V transpose + split
    vtrans_kernel<<<dim3(S / 32, D / 32, NH), dim3(32, 8)>>>(Vf, VThi, VTlo);

    // 7) scores: SC[h] = QW[h] @ KW[h]^T + AK[h]
    gemm_kernel<true, false><<<dim3(S / 128, S / 128, NH), 256, GEMM_SMEM>>>(
        S, S, D, QWhi, QWlo, D, (size_t)S * D, KWhi, KWlo, D, (size_t)S * D,
        SC, S, (size_t)S * S, AK, (size_t)S, nullptr, nullptr);

    // 8) softmax -> bf16 hi/lo probs
    softmax_kernel<<<dim3(S, NH), 256>>>(SC, Phi, Plo);

    // 9) AO[:, h*D:] = P[h] @ VT[h]^T (bf16 hi/lo epilogue)
    gemm_kernel<false, true><<<dim3(1, S / 128, NH), 256, GEMM_SMEM>>>(
        S, D, S, Phi, Plo, S, (size_t)S * S, VThi, VTlo, S, (size_t)D * S,
        nullptr, H, (size_t)D, nullptr, 0, AOhi, AOlo);

    // 10) out = AO @ Wo^T
    gemm_kernel<false, false><<<dim3(H / 128, S / 128, 1), 256, GEMM_SMEM>>>(
        S, H, H, AOhi, AOlo, H, 0, wohi, wolo, H, 0,
        out, H, 0, nullptr, 0, nullptr, nullptr);
}

// round 5
// speedup vs baseline: 2.1047x; 1.0395x over previous
#include <cuda_runtime.h>
#include <cuda_fp16.h>
#include <cstdint>
#include <cstddef>

#define S   2048
#define H   2048
#define NH  16
#define D   128
typedef __half h16;

// ---------------- scratch ----------------------------------------------------
__device__ h16   g_Xhi[(size_t)S * H],  g_Xlo[(size_t)S * H];
__device__ h16   g_wqhi[(size_t)2 * H * H], g_wqlo[(size_t)2 * H * H];
__device__ h16   g_wkhi[(size_t)2 * H * H], g_wklo[(size_t)2 * H * H];
__device__ h16   g_wvhi[(size_t)H * H], g_wvlo[(size_t)H * H];
__device__ h16   g_wohi[(size_t)H * H], g_wolo[(size_t)H * H];
__device__ float g_Qraw[(size_t)S * 2 * H];
__device__ float g_Kraw[(size_t)S * 2 * H];
__device__ float g_Vf[(size_t)S * H];
__device__ h16   g_QWhi[(size_t)NH * S * D], g_QWlo[(size_t)NH * S * D];
__device__ h16   g_KWhi[(size_t)NH * S * D], g_KWlo[(size_t)NH * S * D];
__device__ float g_AK[(size_t)NH * S];
__device__ float g_SC[(size_t)NH * S * S];
__device__ h16   g_Phi[(size_t)NH * S * S], g_Plo[(size_t)NH * S * S];
__device__ h16   g_VThi[(size_t)NH * D * S], g_VTlo[(size_t)NH * D * S];
__device__ h16   g_AOhi[(size_t)S * H], g_AOlo[(size_t)S * H];

// ---------------- helpers -----------------------------------------------------
__device__ __forceinline__ uint32_t smem_u32(const void* p) {
    uint32_t a;
    asm("{ .reg .u64 t; cvta.to.shared.u64 t, %1; cvt.u32.u64 %0, t; }" : "=r"(a) : "l"(p));
    return a;
}
__device__ __forceinline__ void cp16(uint32_t dst, const void* src) {
    asm volatile("cp.async.cg.shared.global [%0], [%1], 16;" :: "r"(dst), "l"(src) : "memory");
}
#define CP_COMMIT() asm volatile("cp.async.commit_group;" ::: "memory")
#define CP_WAIT2()  asm volatile("cp.async.wait_group 2;" ::: "memory")

__device__ __forceinline__ void ldm_x4(uint32_t r[4], uint32_t addr) {
    asm volatile("ldmatrix.sync.aligned.m8n8.x4.shared.b16 {%0,%1,%2,%3}, [%4];"
                 : "=r"(r[0]), "=r"(r[1]), "=r"(r[2]), "=r"(r[3]) : "r"(addr));
}
// fp16 inputs, fp32 accumulate (main term)
__device__ __forceinline__ void mma_f32acc(float c[4], const uint32_t a[4],
                                           uint32_t b0, uint32_t b1) {
    asm volatile(
        "mma.sync.aligned.m16n8k16.row.col.f32.f16.f16.f32 "
        "{%0,%1,%2,%3}, {%4,%5,%6,%7}, {%8,%9}, {%0,%1,%2,%3};"
        : "+f"(c[0]), "+f"(c[1]), "+f"(c[2]), "+f"(c[3])
        : "r"(a[0]), "r"(a[1]), "r"(a[2]), "r"(a[3]), "r"(b0), "r"(b1));
}
// fp16 inputs, fp16 accumulate (small cross terms)
__device__ __forceinline__ void mma_f16acc(uint32_t c[2], const uint32_t a[4],
                                           uint32_t b0, uint32_t b1) {
    asm volatile(
        "mma.sync.aligned.m16n8k16.row.col.f16.f16.f16.f16 "
        "{%0,%1}, {%2,%3,%4,%5}, {%6,%7}, {%0,%1};"
        : "+r"(c[0]), "+r"(c[1])
        : "r"(a[0]), "r"(a[1]), "r"(a[2]), "r"(a[3]), "r"(b0), "r"(b1));
}
__device__ __forceinline__ void split2h(float x, h16& h, h16& l) {
    h = __float2half_rn(x);
    l = __float2half_rn(x - __half2float(h));
}

// ---------------- GEMM: C = (Ahi+Alo)·(Bhi+Blo)^T (+bias[n]) ------------------
// A: [M,K] k-major fp16 hi/lo; B: [N,K] k-major fp16 hi/lo.
// CTA 128x128, BK=32, 8 warps (2m x 4n), 4-stage cp.async pipeline, 1 sync/iter.
#define BK 32
#define MAT_B   8192            // one matrix stage: 2 k16 x 128 rows x 32B
#define STAGE_B (4 * MAT_B)     // Ahi,Alo,Bhi,Blo = 32KB
#define NSTG 4
#define GEMM_SMEM (NSTG * STAGE_B)   // 128KB

__device__ __forceinline__ uint32_t sw_off(int k16, int row, int half) {
    return (uint32_t)(k16 * 4096 + row * 32 + ((half ^ ((row >> 2) & 1)) << 4));
}

template <bool BIAS, bool EPI_F16>
__global__ void __launch_bounds__(256, 1)
gemm_kernel(int M, int N, int K,
            const h16* __restrict__ Ahi, const h16* __restrict__ Alo, int lda, size_t sA,
            const h16* __restrict__ Bhi, const h16* __restrict__ Blo, int ldb, size_t sB,
            float* __restrict__ C, int ldc, size_t sC,
            const float* __restrict__ bias, size_t sBias,
            h16* __restrict__ Chi, h16* __restrict__ Clo)
{
    extern __shared__ char smem[];
    const uint32_t sbase = smem_u32(smem);
    const int tid  = threadIdx.x;
    const int lane = tid & 31;
    const int wid  = tid >> 5;
    const int wm0  = (wid & 1) * 64;
    const int wn0  = (wid >> 1) * 32;

    const int z = blockIdx.z;
    Ahi += (size_t)z * sA;  Alo += (size_t)z * sA;
    Bhi += (size_t)z * sB;  Blo += (size_t)z * sB;
    if (EPI_F16) { Chi += (size_t)z * sC; Clo += (size_t)z * sC; }
    else         { C   += (size_t)z * sC; }
    if (BIAS) bias += (size_t)z * sBias;

    const int m0 = blockIdx.y * 128;
    const int n0 = blockIdx.x * 128;

    // 512 16B-chunks per matrix; 256 threads x 2 chunks
    auto load_stage = [&](int kt, int stg) {
        const int k0 = kt * BK;
        const uint32_t sb = sbase + stg * STAGE_B;
#pragma unroll
        for (int j = 0; j < 2; j++) {
            const int c    = tid + j * 256;       // 0..511
            const int k16  = c >> 8;              // 0..1
            const int row  = (c & 255) >> 1;      // 0..127
            const int half = c & 1;               // 0..1
            const int kel  = k0 + k16 * 16 + half * 8;
            const uint32_t so = sw_off(k16, row, half);
            cp16(sb + so,             Ahi + (size_t)(m0 + row) * lda + kel);
            cp16(sb + MAT_B + so,     Alo + (size_t)(m0 + row) * lda + kel);
            cp16(sb + 2 * MAT_B + so, Bhi + (size_t)(n0 + row) * ldb + kel);
            cp16(sb + 3 * MAT_B + so, Blo + (size_t)(n0 + row) * ldb + kel);
        }
    };

    float acc[4][4][4];
    uint32_t cacc[4][4][2];
#pragma unroll
    for (int i = 0; i < 4; i++)
#pragma unroll
        for (int j = 0; j < 4; j++) {
#pragma unroll
            for (int r = 0; r < 4; r++) acc[i][j][r] = 0.f;
            cacc[i][j][0] = 0u; cacc[i][j][1] = 0u;
        }

    const int nk = K / BK;
    load_stage(0, 0); CP_COMMIT();
    load_stage(1, 1); CP_COMMIT();

    for (int kt = 0; kt < nk; kt++) {
        if (kt + 2 < nk) load_stage(kt + 2, (kt + 2) & 3);
        CP_COMMIT();           // always commit (possibly empty group)
        CP_WAIT2();            // stage kt's group retired
        __syncthreads();

        const uint32_t sb = sbase + (kt & 3) * STAGE_B;
#pragma unroll
        for (int k16 = 0; k16 < 2; k16++) {
            uint32_t ah[4][4], al[4][4];
#pragma unroll
            for (int mt = 0; mt < 4; mt++) {
                const int row = wm0 + mt * 16 + (lane & 15);
                const uint32_t off = sw_off(k16, row, lane >> 4);
                ldm_x4(ah[mt], sb + off);
                ldm_x4(al[mt], sb + MAT_B + off);
            }
            uint32_t bh[2][4], bl[2][4];
#pragma unroll
            for (int g = 0; g < 2; g++) {
                const int row = wn0 + g * 16 + (lane & 15);
                const uint32_t off = sw_off(k16, row, lane >> 4);
                ldm_x4(bh[g], sb + 2 * MAT_B + off);
                ldm_x4(bl[g], sb + 3 * MAT_B + off);
            }
#pragma unroll
            for (int mt = 0; mt < 4; mt++) {
#pragma unroll
                for (int nt = 0; nt < 4; nt++) {
                    const int g = nt >> 1;
                    const int p = nt & 1;
                    const uint32_t b0h = bh[g][p], b1h = bh[g][p + 2];
                    const uint32_t b0l = bl[g][p], b1l = bl[g][p + 2];
                    mma_f32acc(acc[mt][nt], ah[mt], b0h, b1h);   // hi*hi (fp32 acc)
                    mma_f16acc(cacc[mt][nt], ah[mt], b0l, b1l);  // hi*lo (fp16 acc)
                    mma_f16acc(cacc[mt][nt], al[mt], b0h, b1h);  // lo*hi (fp16 acc)
                }
            }
        }
    }

    // ---------------- epilogue ----------------
    const int rbase = m0 + wm0 + (lane >> 2);
    const int cbase = n0 + wn0 + (lane & 3) * 2;
#pragma unroll
    for (int mt = 0; mt < 4; mt++) {
#pragma unroll
        for (int nt = 0; nt < 4; nt++) {
            const int row = rbase + mt * 16;
            const int col = cbase + nt * 8;
            float2 c01 = __half22float2(*reinterpret_cast<__half2*>(&cacc[mt][nt][0]));
            float2 c23 = __half22float2(*reinterpret_cast<__half2*>(&cacc[mt][nt][1]));
            float v0 = acc[mt][nt][0] + c01.x, v1 = acc[mt][nt][1] + c01.y;
            float v2 = acc[mt][nt][2] + c23.x, v3 = acc[mt][nt][3] + c23.y;
            if (BIAS) {
                const float b0 = __ldg(bias + col), b1 = __ldg(bias + col + 1);
                v0 += b0; v1 += b1; v2 += b0; v3 += b1;
            }
            if (EPI_F16) {
                h16 h0, l0, h1, l1;
                split2h(v0, h0, l0); split2h(v1, h1, l1);
                __half2 hp, lp;
                hp.x = h0; hp.y = h1; lp.x = l0; lp.y = l1;
                *reinterpret_cast<__half2*>(Chi + (size_t)row * ldc + col) = hp;
                *reinterpret_cast<__half2*>(Clo + (size_t)row * ldc + col) = lp;
                split2h(v2, h0, l0); split2h(v3, h1, l1);
                hp.x = h0; hp.y = h1; lp.x = l0; lp.y = l1;
                *reinterpret_cast<__half2*>(Chi + (size_t)(row + 8) * ldc + col) = hp;
                *reinterpret_cast<__half2*>(Clo + (size_t)(row + 8) * ldc + col) = lp;
            } else {
                *reinterpret_cast<float2*>(C + (size_t)row * ldc + col)       = make_float2(v0, v1);
                *reinterpret_cast<float2*>(C + (size_t)(row + 8) * ldc + col) = make_float2(v2, v3);
            }
        }
    }
}

// ---------------- fp32 -> fp16 hi/lo split -----------------------------------
__global__ void split_kernel(const float* __restrict__ x, h16* __restrict__ hi,
                             h16* __restrict__ lo, int n4)
{
    int i = blockIdx.x * blockDim.x + threadIdx.x;
    if (i >= n4) return;
    float4 v = reinterpret_cast<const float4*>(x)[i];
    h16 h[4], l[4];
    split2h(v.x, h[0], l[0]); split2h(v.y, h[1], l[1]);
    split2h(v.z, h[2], l[2]); split2h(v.w, h[3], l[3]);
    __half2 hp0, hp1, lp0, lp1;
    hp0.x = h[0]; hp0.y = h[1]; hp1.x = h[2]; hp1.y = h[3];
    lp0.x = l[0]; lp0.y = l[1]; lp1.x = l[2]; lp1.y = l[3];
    reinterpret_cast<__half2*>(hi)[i * 2]     = hp0;
    reinterpret_cast<__half2*>(hi)[i * 2 + 1] = hp1;
    reinterpret_cast<__half2*>(lo)[i * 2]     = lp0;
    reinterpret_cast<__half2*>(lo)[i * 2 + 1] = lp1;
}

// ---------------- softplus + variance weighting + RoPE (Q and K fused) -------
__global__ void __launch_bounds__(128)
transform2_kernel(const float* __restrict__ rawQ, const float* __restrict__ rawK,
                  const float* __restrict__ cosT, const float* __restrict__ sinT,
                  h16* __restrict__ QWhi, h16* __restrict__ QWlo,
                  h16* __restrict__ KWhi, h16* __restrict__ KWlo,
                  float* __restrict__ AK)
{
    const int s = blockIdx.x, h = blockIdx.y, zz = blockIdx.z, d = threadIdx.x;
    const float* raw = zz ? rawK : rawQ;
    h16* Whi = zz ? KWhi : QWhi;
    h16* Wlo = zz ? KWlo : QWlo;

    const float* base = raw + (size_t)s * (2 * H) + h * (2 * D);
    float mu = base[d];
    float sr = base[D + d];
    float sp = (sr > 20.f) ? sr : log1pf(expf(sr));
    float sigma = sp + 1e-4f;
    float w = mu * rsqrtf(sigma);

    __shared__ float sw[D];
    sw[d] = w;
    __syncthreads();
    float rh = (d < 64) ? -sw[d + 64] : sw[d - 64];
    float wr = w * cosT[(size_t)s * D + d] + rh * sinT[(size_t)s * D + d];

    h16 hh, ll;
    split2h(wr, hh, ll);
    const size_t o = ((size_t)h * S + s) * D + d;
    Whi[o] = hh;  Wlo[o] = ll;

    if (zz) {
        __shared__ float red[D];
        red[d] = wr * wr + logf(sigma);
        __syncthreads();
#pragma unroll
        for (int o2 = 64; o2 > 0; o2 >>= 1) {
            if (d < o2) red[d] += red[d + o2];
            __syncthreads();
        }
        if (d == 0) AK[(size_t)h * S + s] = -0.5f * red[0];
    }
}

// ---------------- V transpose + split ----------------------------------------
__global__ void vtrans_kernel(const float* __restrict__ V,
                              h16* __restrict__ VThi, h16* __restrict__ VTlo)
{
    __shared__ float tile[32][33];
    const int s0 = blockIdx.x * 32, d0 = blockIdx.y * 32, h = blockIdx.z;
    const int tx = threadIdx.x, ty = threadIdx.y;
#pragma unroll
    for (int j = 0; j < 4; j++) {
        int r = ty + j * 8;
        tile[r][tx] = V[(size_t)(s0 + r) * H + h * D + d0 + tx];
    }
    __syncthreads();
#pragma unroll
    for (int j = 0; j < 4; j++) {
        int dr = ty + j * 8;
        float v = tile[tx][dr];
        h16 hh, ll;
        split2h(v, hh, ll);
        size_t o = ((size_t)h * D + d0 + dr) * S + s0 + tx;
        VThi[o] = hh;  VTlo[o] = ll;
    }
}

// ---------------- register-resident softmax -> fp16 hi/lo probs --------------
__global__ void __launch_bounds__(256)
softmax_kernel(const float* __restrict__ SC, h16* __restrict__ Phi, h16* __restrict__ Plo)
{
    const int q = blockIdx.x, h = blockIdx.y, t = threadIdx.x;
    const size_t base = ((size_t)h * S + q) * S;
    const float* row = SC + base;

    float v[8];
    float4 a = *reinterpret_cast<const float4*>(row + t * 8);
    float4 b = *reinterpret_cast<const float4*>(row + t * 8 + 4);
    v[0] = a.x; v[1] = a.y; v[2] = a.z; v[3] = a.w;
    v[4] = b.x; v[5] = b.y; v[6] = b.z; v[7] = b.w;

    __shared__ float red[256];
    float m = v[0];
#pragma unroll
    for (int i = 1; i < 8; i++) m = fmaxf(m, v[i]);
    red[t] = m;
    __syncthreads();
#pragma unroll
    for (int o = 128; o > 0; o >>= 1) {
        if (t < o) red[t] = fmaxf(red[t], red[t + o]);
        __syncthreads();
    }
    m = red[0];
    __syncthreads();

    float sum = 0.f;
#pragma unroll
    for (int i = 0; i < 8; i++) { v[i] = __expf(v[i] - m); sum += v[i]; }
    red[t] = sum;
    __syncthreads();
#pragma unroll
    for (int o = 128; o > 0; o >>= 1) {
        if (t < o) red[t] += red[t + o];
        __syncthreads();
    }
    const float inv = 1.f / red[0];

#pragma unroll
    for (int j = 0; j < 4; j++) {
        float p0 = v[2 * j] * inv, p1 = v[2 * j + 1] * inv;
        h16 h0, l0, h1, l1;
        split2h(p0, h0, l0); split2h(p1, h1, l1);
        __half2 hp, lp;
        hp.x = h0; hp.y = h1; lp.x = l0; lp.y = l1;
        *reinterpret_cast<__half2*>(Phi + base + t * 8 + 2 * j) = hp;
        *reinterpret_cast<__half2*>(Plo + base + t * 8 + 2 * j) = lp;
    }
}

// ---------------- launch ------------------------------------------------------
extern "C" void kernel_launch(void* const* d_in, const int* in_sizes, int n_in,
                              void* d_out, int out_size)
{
    const float* X    = (const float*)d_in[0];
    const float* cosT = (const float*)d_in[1];
    const float* sinT = (const float*)d_in[2];
    const float* w_q  = (const float*)d_in[3];
    const float* w_k  = (const float*)d_in[4];
    const float* w_v  = (const float*)d_in[5];
    const float* w_o  = (const float*)d_in[6];
    float* out = (float*)d_out;

    h16 *Xhi, *Xlo, *wqhi, *wqlo, *wkhi, *wklo, *wvhi, *wvlo, *wohi, *wolo;
    float *Qraw, *Kraw, *Vf, *AK, *SC;
    h16 *QWhi, *QWlo, *KWhi, *KWlo, *Phi, *Plo, *VThi, *VTlo, *AOhi, *AOlo;
    cudaGetSymbolAddress((void**)&Xhi, g_Xhi);   cudaGetSymbolAddress((void**)&Xlo, g_Xlo);
    cudaGetSymbolAddress((void**)&wqhi, g_wqhi); cudaGetSymbolAddress((void**)&wqlo, g_wqlo);
    cudaGetSymbolAddress((void**)&wkhi, g_wkhi); cudaGetSymbolAddress((void**)&wklo, g_wklo);
    cudaGetSymbolAddress((void**)&wvhi, g_wvhi); cudaGetSymbolAddress((void**)&wvlo, g_wvlo);
    cudaGetSymbolAddress((void**)&wohi, g_wohi); cudaGetSymbolAddress((void**)&wolo, g_wolo);
    cudaGetSymbolAddress((void**)&Qraw, g_Qraw); cudaGetSymbolAddress((void**)&Kraw, g_Kraw);
    cudaGetSymbolAddress((void**)&Vf, g_Vf);
    cudaGetSymbolAddress((void**)&QWhi, g_QWhi); cudaGetSymbolAddress((void**)&QWlo, g_QWlo);
    cudaGetSymbolAddress((void**)&KWhi, g_KWhi); cudaGetSymbolAddress((void**)&KWlo, g_KWlo);
    cudaGetSymbolAddress((void**)&AK, g_AK);     cudaGetSymbolAddress((void**)&SC, g_SC);
    cudaGetSymbolAddress((void**)&Phi, g_Phi);   cudaGetSymbolAddress((void**)&Plo, g_Plo);
    cudaGetSymbolAddress((void**)&VThi, g_VThi); cudaGetSymbolAddress((void**)&VTlo, g_VTlo);
    cudaGetSymbolAddress((void**)&AOhi, g_AOhi); cudaGetSymbolAddress((void**)&AOlo, g_AOlo);

    cudaFuncSetAttribute(gemm_kernel<false, false>,
                         cudaFuncAttributeMaxDynamicSharedMemorySize, GEMM_SMEM);
    cudaFuncSetAttribute(gemm_kernel<true, false>,
                         cudaFuncAttributeMaxDynamicSharedMemorySize, GEMM_SMEM);
    cudaFuncSetAttribute(gemm_kernel<false, true>,
                         cudaFuncAttributeMaxDynamicSharedMemorySize, GEMM_SMEM);

    auto launch_split = [](const float* x, h16* hi, h16* lo, size_t n) {
        int n4 = (int)(n / 4);
        split_kernel<<<(n4 + 255) / 256, 256>>>(x, hi, lo, n4);
    };
    launch_split(X,   Xhi,  Xlo,  (size_t)S * H);
    launch_split(w_q, wqhi, wqlo, (size_t)2 * H * H);
    launch_split(w_k, wkhi, wklo, (size_t)2 * H * H);
    launch_split(w_v, wvhi, wvlo, (size_t)H * H);
    launch_split(w_o, wohi, wolo, (size_t)H * H);

    // projections
    gemm_kernel<false, false><<<dim3(4096 / 128, S / 128, 1), 256, GEMM_SMEM>>>(
        S, 4096, H, Xhi, Xlo, H, 0, wqhi, wqlo, H, 0,
        Qraw, 4096, 0, nullptr, 0, nullptr, nullptr);
    gemm_kernel<false, false><<<dim3(4096 / 128, S / 128, 1), 256, GEMM_SMEM>>>(
        S, 4096, H, Xhi, Xlo, H, 0, wkhi, wklo, H, 0,
        Kraw, 4096, 0, nullptr, 0, nullptr, nullptr);
    gemm_kernel<false, false><<<dim3(H / 128, S / 128, 1), 256, GEMM_SMEM>>>(
        S, H, H, Xhi, Xlo, H, 0, wvhi, wvlo, H, 0,
        Vf, H, 0, nullptr, 0, nullptr, nullptr);

    // transforms (Q z=0, K z=1 fused)
    transform2_kernel<<<dim3(S, NH, 2), 128>>>(Qraw, Kraw, cosT, sinT,
                                               QWhi, QWlo, KWhi, KWlo, AK);

    // V transpose + split
    vtrans_kernel<<<dim3(S / 32, D / 32, NH), dim3(32, 8)>>>(Vf, VThi, VTlo);

    // scores: SC[h] = QW[h] @ KW[h]^T + AK[h]
    gemm_kernel<true, false><<<dim3(S / 128, S / 128, NH), 256, GEMM_SMEM>>>(
        S, S, D, QWhi, QWlo, D, (size_t)S * D, KWhi, KWlo, D, (size_t)S * D,
        SC, S, (size_t)S * S, AK, (size_t)S, nullptr, nullptr);

    // softmax -> fp16 hi/lo probs
    softmax_kernel<<<dim3(S, NH), 256>>>(SC, Phi, Plo);

    // AO[:, h*D:] = P[h] @ VT[h]^T (fp16 hi/lo epilogue)
    gemm_kernel<false, true><<<dim3(1, S / 128, NH), 256, GEMM_SMEM>>>(
        S, D, S, Phi, Plo, S, (size_t)S * S, VThi, VTlo, S, (size_t)D * S,
        nullptr, H, (size_t)D, nullptr, 0, AOhi, AOlo);

    // out = AO @ Wo^T
    gemm_kernel<false, false><<<dim3(H / 128, S / 128, 1), 256, GEMM_SMEM>>>(
        S, H, H, AOhi, AOlo, H, 0, wohi, wolo, H, 0,
        out, H, 0, nullptr, 0, nullptr, nullptr);
}